// round 3
// baseline (speedup 1.0000x reference)
#include <cuda_runtime.h>

// Problem constants
#define BB   2
#define SS   2048
#define HIDD 4096
#define NH   32
#define NKV  8
#define HD   128

// ---------------- scratch (static device globals; no runtime alloc) --------
__device__ float g_qproj[(size_t)BB * SS * HIDD];            // 67 MB
__device__ float g_kvproj[(size_t)BB * SS * 2 * NKV * HD];   // 33 MB
__device__ float g_q[(size_t)BB * NH * SS * HD];             // 67 MB
__device__ float g_k[(size_t)BB * NKV * SS * HD];            // 17 MB
__device__ float g_v[(size_t)BB * NKV * SS * HD];            // 17 MB
__device__ float g_attn[(size_t)BB * SS * HIDD];             // 67 MB

// ---------------------------------------------------------------------------
// GEMM: C[M,N] = A[M,K] @ W[N,K]^T (+ bias[N])
// 128x128 block tile, BK=16, 8x8 per thread, 256 threads.
// ---------------------------------------------------------------------------
template <int BIAS>
__global__ __launch_bounds__(256) void gemm_nt(const float* __restrict__ A,
                                               const float* __restrict__ W,
                                               const float* __restrict__ bias,
                                               float* __restrict__ C,
                                               int M, int N, int K) {
  __shared__ float As[16][132];
  __shared__ float Bs[16][132];
  const int bm = blockIdx.y * 128;
  const int bn = blockIdx.x * 128;
  const int tid = threadIdx.x;
  const int tr = tid >> 4;   // 0..15
  const int tc = tid & 15;   // 0..15

  float acc[8][8];
#pragma unroll
  for (int i = 0; i < 8; i++)
#pragma unroll
    for (int j = 0; j < 8; j++) acc[i][j] = 0.0f;

  const float* Aptr = A + (size_t)bm * K;
  const float* Wptr = W + (size_t)bn * K;

  for (int k0 = 0; k0 < K; k0 += 16) {
#pragma unroll
    for (int i = 0; i < 2; i++) {
      int idx = tid + i * 256;       // 0..511
      int row = idx >> 2;            // 0..127
      int c4  = idx & 3;             // which float4 of the 16-wide k slab
      float4 av = *(const float4*)(Aptr + (size_t)row * K + k0 + c4 * 4);
      float4 wv = *(const float4*)(Wptr + (size_t)row * K + k0 + c4 * 4);
      As[c4 * 4 + 0][row] = av.x; As[c4 * 4 + 1][row] = av.y;
      As[c4 * 4 + 2][row] = av.z; As[c4 * 4 + 3][row] = av.w;
      Bs[c4 * 4 + 0][row] = wv.x; Bs[c4 * 4 + 1][row] = wv.y;
      Bs[c4 * 4 + 2][row] = wv.z; Bs[c4 * 4 + 3][row] = wv.w;
    }
    __syncthreads();

#pragma unroll
    for (int kk = 0; kk < 16; kk++) {
      float4 a0 = *(const float4*)&As[kk][tr * 4];
      float4 a1 = *(const float4*)&As[kk][64 + tr * 4];
      float4 b0 = *(const float4*)&Bs[kk][tc * 4];
      float4 b1 = *(const float4*)&Bs[kk][64 + tc * 4];
      float a[8] = {a0.x, a0.y, a0.z, a0.w, a1.x, a1.y, a1.z, a1.w};
      float b[8] = {b0.x, b0.y, b0.z, b0.w, b1.x, b1.y, b1.z, b1.w};
#pragma unroll
      for (int i = 0; i < 8; i++)
#pragma unroll
        for (int j = 0; j < 8; j++) acc[i][j] = fmaf(a[i], b[j], acc[i][j]);
    }
    __syncthreads();
  }

#pragma unroll
  for (int i = 0; i < 8; i++) {
    int row = bm + ((i < 4) ? (tr * 4 + i) : (64 + tr * 4 + i - 4));
#pragma unroll
    for (int jg = 0; jg < 2; jg++) {
      int col = bn + jg * 64 + tc * 4;
      float4 v;
      v.x = acc[i][jg * 4 + 0];
      v.y = acc[i][jg * 4 + 1];
      v.z = acc[i][jg * 4 + 2];
      v.w = acc[i][jg * 4 + 3];
      if (BIAS) {
        v.x += bias[col + 0]; v.y += bias[col + 1];
        v.z += bias[col + 2]; v.w += bias[col + 3];
      }
      *(float4*)(C + (size_t)row * N + col) = v;
    }
  }
}

// ---------------------------------------------------------------------------
// RoPE for Q + scatter to [B, NH, S, HD]
// ---------------------------------------------------------------------------
__global__ __launch_bounds__(256) void rope_q_kernel(
    const float* __restrict__ cosb, const float* __restrict__ sinb) {
  int idx = blockIdx.x * 256 + threadIdx.x;  // (b, s, h, d) packed, 2^24 total
  int d = idx & 127;
  int h = (idx >> 7) & 31;
  int s = (idx >> 12) & 2047;
  int b = idx >> 23;
  float v = g_qproj[idx];
  float p = (d < 64) ? -g_qproj[idx + 64] : g_qproj[idx - 64];
  float out = v * cosb[s * HD + d] + p * sinb[s * HD + d];
  g_q[((size_t)(b * NH + h) * SS + s) * HD + d] = out;
}

// ---------------------------------------------------------------------------
// RoPE for K + scatter K/V to [B, NKV, S, HD]
// ---------------------------------------------------------------------------
__global__ __launch_bounds__(256) void rope_kv_kernel(
    const float* __restrict__ cosb, const float* __restrict__ sinb) {
  int idx = blockIdx.x * 256 + threadIdx.x;  // (b, s, n, d) packed, 2^22 total
  int d = idx & 127;
  int n = (idx >> 7) & 7;
  int s = (idx >> 10) & 2047;
  int b = idx >> 21;
  size_t base = ((size_t)(b * SS + s) * (2 * NKV * HD)) + n * (2 * HD);
  float kv = g_kvproj[base + d];
  float kp = (d < 64) ? -g_kvproj[base + d + 64] : g_kvproj[base + d - 64];
  float kout = kv * cosb[s * HD + d] + kp * sinb[s * HD + d];
  size_t o = ((size_t)(b * NKV + n) * SS + s) * HD + d;
  g_k[o] = kout;
  g_v[o] = g_kvproj[base + HD + d];
}

// ---------------------------------------------------------------------------
// Causal flash attention: 32 q-rows per CTA, stream 32-key blocks.
// 256 threads: thread t -> q row r = t/8, group g = t%8.
//   - scores: 4 per thread, columns j in {g, g+8, g+16, g+24}
//   - output: 16 columns per thread, cols [g*16, g*16+16)
// Output written transposed back into g_attn[b, s, h*HD + d].
// ---------------------------------------------------------------------------
__global__ __launch_bounds__(256) void attn_kernel() {
  extern __shared__ float sm[];
  float* Qs = sm;                 // 32 x 128
  float* Ks = Qs + 32 * 128;      // 32 x 132 (padded)
  float* Vs = Ks + 32 * 132;      // 32 x 128
  float* Ps = Vs + 32 * 128;      // 32 x 33  (padded)

  const int b = blockIdx.z;
  const int h = blockIdx.y;
  const int q0 = blockIdx.x * 32;
  const int kvh = h / (NH / NKV);
  const int tid = threadIdx.x;
  const int r = tid >> 3;  // q row in tile
  const int g = tid & 7;   // column group

  const float* Qg = g_q + ((size_t)(b * NH + h) * SS + q0) * HD;
  const float* Kg = g_k + (size_t)(b * NKV + kvh) * SS * HD;
  const float* Vg = g_v + (size_t)(b * NKV + kvh) * SS * HD;

  // load Q tile (32x128 floats), float4 coalesced
#pragma unroll
  for (int i = 0; i < 4; i++) {
    int idx = tid + i * 256;   // 0..1023 float4s
    int row = idx >> 5, c4 = idx & 31;
    *(float4*)(Qs + row * 128 + c4 * 4) = *(const float4*)(Qg + row * HD + c4 * 4);
  }

  float acc[16];
#pragma unroll
  for (int i = 0; i < 16; i++) acc[i] = 0.0f;
  float m = -1e30f, l = 0.0f;

  const float scale = 0.08838834764831845f;  // 1/sqrt(128)
  const int nkb = blockIdx.x + 1;            // causal: only blocks up to diag

  for (int kb = 0; kb < nkb; kb++) {
    const int k0 = kb * 32;
    // load K/V block
#pragma unroll
    for (int i = 0; i < 4; i++) {
      int idx = tid + i * 256;
      int row = idx >> 5, c4 = idx & 31;
      *(float4*)(Ks + row * 132 + c4 * 4) = *(const float4*)(Kg + (k0 + row) * HD + c4 * 4);
      *(float4*)(Vs + row * 128 + c4 * 4) = *(const float4*)(Vg + (k0 + row) * HD + c4 * 4);
    }
    __syncthreads();

    // scores: 4 dots of length 128
    float s0 = 0.f, s1 = 0.f, s2 = 0.f, s3 = 0.f;
    const float4* qrow = (const float4*)(Qs + r * 128);
    const float4* kr0 = (const float4*)(Ks + (g + 0) * 132);
    const float4* kr1 = (const float4*)(Ks + (g + 8) * 132);
    const float4* kr2 = (const float4*)(Ks + (g + 16) * 132);
    const float4* kr3 = (const float4*)(Ks + (g + 24) * 132);
#pragma unroll
    for (int d4 = 0; d4 < 32; d4++) {
      float4 q4 = qrow[d4];
      float4 k4;
      k4 = kr0[d4];
      s0 = fmaf(q4.x, k4.x, fmaf(q4.y, k4.y, fmaf(q4.z, k4.z, fmaf(q4.w, k4.w, s0))));
      k4 = kr1[d4];
      s1 = fmaf(q4.x, k4.x, fmaf(q4.y, k4.y, fmaf(q4.z, k4.z, fmaf(q4.w, k4.w, s1))));
      k4 = kr2[d4];
      s2 = fmaf(q4.x, k4.x, fmaf(q4.y, k4.y, fmaf(q4.z, k4.z, fmaf(q4.w, k4.w, s2))));
      k4 = kr3[d4];
      s3 = fmaf(q4.x, k4.x, fmaf(q4.y, k4.y, fmaf(q4.z, k4.z, fmaf(q4.w, k4.w, s3))));
    }
    const int qg = q0 + r;
    float sc[4] = {s0, s1, s2, s3};
#pragma unroll
    for (int jj = 0; jj < 4; jj++) {
      int kg = k0 + g + jj * 8;
      sc[jj] = sc[jj] * scale + ((kg > qg) ? -1e9f : 0.0f);
    }

    // row max across the 8 threads of this row (consecutive lanes)
    float rowmax = fmaxf(fmaxf(sc[0], sc[1]), fmaxf(sc[2], sc[3]));
#pragma unroll
    for (int msk = 1; msk < 8; msk <<= 1)
      rowmax = fmaxf(rowmax, __shfl_xor_sync(0xffffffffu, rowmax, msk));

    float m_new = fmaxf(m, rowmax);
    float corr = __expf(m - m_new);
    float p[4], psum = 0.f;
#pragma unroll
    for (int jj = 0; jj < 4; jj++) {
      p[jj] = __expf(sc[jj] - m_new);
      psum += p[jj];
    }
#pragma unroll
    for (int msk = 1; msk < 8; msk <<= 1)
      psum += __shfl_xor_sync(0xffffffffu, psum, msk);
    l = l * corr + psum;
    m = m_new;
#pragma unroll
    for (int i = 0; i < 16; i++) acc[i] *= corr;

#pragma unroll
    for (int jj = 0; jj < 4; jj++) Ps[r * 33 + g + jj * 8] = p[jj];
    __syncthreads();

    // O += P @ V   (16 output cols per thread)
#pragma unroll 4
    for (int j = 0; j < 32; j++) {
      float pv = Ps[r * 33 + j];
      const float4* vr = (const float4*)(Vs + j * 128 + g * 16);
#pragma unroll
      for (int u = 0; u < 4; u++) {
        float4 v4 = vr[u];
        acc[u * 4 + 0] = fmaf(pv, v4.x, acc[u * 4 + 0]);
        acc[u * 4 + 1] = fmaf(pv, v4.y, acc[u * 4 + 1]);
        acc[u * 4 + 2] = fmaf(pv, v4.z, acc[u * 4 + 2]);
        acc[u * 4 + 3] = fmaf(pv, v4.w, acc[u * 4 + 3]);
      }
    }
    __syncthreads();
  }

  float inv = 1.0f / l;
  float* outp = g_attn + ((size_t)(b * SS + q0 + r)) * HIDD + h * HD + g * 16;
#pragma unroll
  for (int u = 0; u < 4; u++) {
    float4 v4;
    v4.x = acc[u * 4 + 0] * inv;
    v4.y = acc[u * 4 + 1] * inv;
    v4.z = acc[u * 4 + 2] * inv;
    v4.w = acc[u * 4 + 3] * inv;
    *(float4*)(outp + u * 4) = v4;
  }
}

// ---------------------------------------------------------------------------
extern "C" void kernel_launch(void* const* d_in, const int* in_sizes, int n_in,
                              void* d_out, int out_size) {
  const float* hidden = (const float*)d_in[0];
  // d_in[1] = attention_mask (pure causal -1e9; applied analytically)
  const float* cosb = (const float*)d_in[2];
  const float* sinb = (const float*)d_in[3];
  const float* Wq = (const float*)d_in[4];
  const float* Wkv = (const float*)d_in[5];
  const float* Wd = (const float*)d_in[6];
  const float* bd = (const float*)d_in[7];
  float* out = (float*)d_out;

  float *qproj, *kvproj, *attn;
  cudaGetSymbolAddress((void**)&qproj, g_qproj);
  cudaGetSymbolAddress((void**)&kvproj, g_kvproj);
  cudaGetSymbolAddress((void**)&attn, g_attn);

  const int M = BB * SS;  // 4096

  // 1) Q projection: [M, 4096] = hidden @ Wq^T
  {
    dim3 grid(HIDD / 128, M / 128);
    gemm_nt<0><<<grid, 256>>>(hidden, Wq, nullptr, qproj, M, HIDD, HIDD);
  }
  // 2) KV projection: [M, 2048] = hidden @ Wkv^T
  {
    dim3 grid((2 * NKV * HD) / 128, M / 128);
    gemm_nt<0><<<grid, 256>>>(hidden, Wkv, nullptr, kvproj, M, 2 * NKV * HD, HIDD);
  }
  // 3) RoPE + scatter
  rope_q_kernel<<<(BB * SS * HIDD) / 256, 256>>>(cosb, sinb);
  rope_kv_kernel<<<(BB * SS * NKV * HD) / 256, 256>>>(cosb, sinb);

  // 4) attention
  {
    int smem = (32 * 128 + 32 * 132 + 32 * 128 + 32 * 33) * 4;  // 53888 B
    cudaFuncSetAttribute(attn_kernel, cudaFuncAttributeMaxDynamicSharedMemorySize, smem);
    dim3 grid(SS / 32, NH, BB);
    attn_kernel<<<grid, 256, smem>>>();
  }

  // 5) output projection with bias: out = attn @ Wd^T + bd
  {
    dim3 grid(HIDD / 128, M / 128);
    gemm_nt<1><<<grid, 256>>>(attn, Wd, bd, out, M, HIDD, HIDD);
  }
}

// round 5
// speedup vs baseline: 1.3760x; 1.3760x over previous
#include <cuda_runtime.h>
#include <cstdint>

// Problem constants
#define BB   2
#define SS   2048
#define HIDD 4096
#define NH   32
#define NKV  8
#define HD   128

// GEMM tiling
#define BM 128
#define BN 128
#define BKK 32
#define LDK 36                      // padded k-row length (floats)
#define STAGE_FLOATS ((BM + BN) * LDK)   // 9216 floats = 36 KB per stage

// ---------------- scratch (static device globals; no runtime alloc) --------
__device__ float g_qproj[(size_t)BB * SS * HIDD];            // 67 MB
__device__ float g_kvproj[(size_t)BB * SS * 2 * NKV * HD];   // 33 MB
__device__ float g_q[(size_t)BB * NH * SS * HD];             // 67 MB
__device__ float g_k[(size_t)BB * NKV * SS * HD];            // 17 MB
__device__ float g_v[(size_t)BB * NKV * SS * HD];            // 17 MB
__device__ float g_attn[(size_t)BB * SS * HIDD];             // 67 MB

// ---------------------------------------------------------------------------
// helpers
// ---------------------------------------------------------------------------
__device__ __forceinline__ uint32_t cvta_smem(const void* p) {
  return (uint32_t)__cvta_generic_to_shared(p);
}

__device__ __forceinline__ void cp_async16(uint32_t saddr, const void* gptr) {
  asm volatile("cp.async.cg.shared.global [%0], [%1], 16;\n" ::"r"(saddr), "l"(gptr));
}

__device__ __forceinline__ uint32_t f2tf32(float x) {
  uint32_t u;
  asm("cvt.rna.tf32.f32 %0, %1;\n" : "=r"(u) : "f"(x));
  return u;
}

// ---------------------------------------------------------------------------
// TF32 tensor-core GEMM: C[M,N] = A[M,K] @ W[N,K]^T (+ bias[N])
// 128x128x32 CTA tile, 8 warps (2x4), warp tile 64x32, mma m16n8k8.
// 2-stage cp.async pipeline. Dynamic smem = 2 * 36 KB.
// ---------------------------------------------------------------------------
template <int BIAS>
__global__ __launch_bounds__(256, 2) void gemm_tf32(const float* __restrict__ A,
                                                    const float* __restrict__ W,
                                                    const float* __restrict__ bias,
                                                    float* __restrict__ C,
                                                    int M, int N, int K) {
  extern __shared__ float sm[];
  const int bm = blockIdx.y * BM;
  const int bn = blockIdx.x * BN;
  const int tid = threadIdx.x;
  const int warp = tid >> 5;
  const int lane = tid & 31;
  const int g = lane >> 2;   // groupID 0..7
  const int t = lane & 3;    // threadID_in_group 0..3
  const int wm = (warp >> 2) * 64;  // warp row offset in tile
  const int wn = (warp & 3) * 32;   // warp col offset in tile

  const float* Ag = A + (size_t)bm * K;
  const float* Wg = W + (size_t)bn * K;

  // per-thread global->smem assignments: 4 float4 each for A and B per BK slab
  // lin = tid + i*256 in [0,1024): row = lin>>3 (0..127), c4 = lin&7 (0..7)
  const int KT = K / BKK;

  float acc[4][4][4];
#pragma unroll
  for (int mi = 0; mi < 4; mi++)
#pragma unroll
    for (int ni = 0; ni < 4; ni++)
#pragma unroll
      for (int c = 0; c < 4; c++) acc[mi][ni][c] = 0.0f;

  // issue stage loads for slab kb into buffer (kb & 1)
  auto issue = [&](int kb) {
    float* As = sm + (kb & 1) * STAGE_FLOATS;
    float* Ws = As + BM * LDK;
    int k0 = kb * BKK;
#pragma unroll
    for (int i = 0; i < 4; i++) {
      int lin = tid + i * 256;
      int row = lin >> 3;
      int c4 = lin & 7;
      cp_async16(cvta_smem(As + row * LDK + c4 * 4),
                 Ag + (size_t)row * K + k0 + c4 * 4);
      cp_async16(cvta_smem(Ws + row * LDK + c4 * 4),
                 Wg + (size_t)row * K + k0 + c4 * 4);
    }
    asm volatile("cp.async.commit_group;\n" ::);
  };

  issue(0);

  for (int kb = 0; kb < KT; kb++) {
    if (kb + 1 < KT) {
      issue(kb + 1);
      asm volatile("cp.async.wait_group 1;\n" ::);
    } else {
      asm volatile("cp.async.wait_group 0;\n" ::);
    }
    __syncthreads();

    const float* As = sm + (kb & 1) * STAGE_FLOATS;
    const float* Ws = As + BM * LDK;

#pragma unroll
    for (int ks = 0; ks < 4; ks++) {
      const int k0 = ks * 8;
      uint32_t af[4][4];
      uint32_t bf[4][2];
#pragma unroll
      for (int mi = 0; mi < 4; mi++) {
        const float* p0 = As + (wm + mi * 16 + g) * LDK + k0 + t;
        const float* p1 = p0 + 8 * LDK;
        af[mi][0] = f2tf32(p0[0]);
        af[mi][1] = f2tf32(p1[0]);
        af[mi][2] = f2tf32(p0[4]);
        af[mi][3] = f2tf32(p1[4]);
      }
#pragma unroll
      for (int ni = 0; ni < 4; ni++) {
        const float* p = Ws + (wn + ni * 8 + g) * LDK + k0 + t;
        bf[ni][0] = f2tf32(p[0]);
        bf[ni][1] = f2tf32(p[4]);
      }
#pragma unroll
      for (int mi = 0; mi < 4; mi++)
#pragma unroll
        for (int ni = 0; ni < 4; ni++) {
          asm volatile(
              "mma.sync.aligned.m16n8k8.row.col.f32.tf32.tf32.f32 "
              "{%0,%1,%2,%3}, {%4,%5,%6,%7}, {%8,%9}, {%0,%1,%2,%3};\n"
              : "+f"(acc[mi][ni][0]), "+f"(acc[mi][ni][1]),
                "+f"(acc[mi][ni][2]), "+f"(acc[mi][ni][3])
              : "r"(af[mi][0]), "r"(af[mi][1]), "r"(af[mi][2]), "r"(af[mi][3]),
                "r"(bf[ni][0]), "r"(bf[ni][1]));
        }
    }
    __syncthreads();
  }

  // epilogue
#pragma unroll
  for (int mi = 0; mi < 4; mi++) {
    int row0 = bm + wm + mi * 16 + g;
#pragma unroll
    for (int ni = 0; ni < 4; ni++) {
      int col = bn + wn + ni * 8 + t * 2;
      float b0 = 0.f, b1 = 0.f;
      if (BIAS) { b0 = bias[col]; b1 = bias[col + 1]; }
      float2 v0 = make_float2(acc[mi][ni][0] + b0, acc[mi][ni][1] + b1);
      float2 v1 = make_float2(acc[mi][ni][2] + b0, acc[mi][ni][3] + b1);
      *(float2*)(C + (size_t)row0 * N + col) = v0;
      *(float2*)(C + (size_t)(row0 + 8) * N + col) = v1;
    }
  }
}

// ---------------------------------------------------------------------------
// RoPE for Q + scatter to [B, NH, S, HD]
// ---------------------------------------------------------------------------
__global__ __launch_bounds__(256) void rope_q_kernel(
    const float* __restrict__ cosb, const float* __restrict__ sinb) {
  int idx = blockIdx.x * 256 + threadIdx.x;
  int d = idx & 127;
  int h = (idx >> 7) & 31;
  int s = (idx >> 12) & 2047;
  int b = idx >> 23;
  float v = g_qproj[idx];
  float p = (d < 64) ? -g_qproj[idx + 64] : g_qproj[idx - 64];
  float out = v * cosb[s * HD + d] + p * sinb[s * HD + d];
  g_q[((size_t)(b * NH + h) * SS + s) * HD + d] = out;
}

// ---------------------------------------------------------------------------
// RoPE for K + scatter K/V to [B, NKV, S, HD]
// ---------------------------------------------------------------------------
__global__ __launch_bounds__(256) void rope_kv_kernel(
    const float* __restrict__ cosb, const float* __restrict__ sinb) {
  int idx = blockIdx.x * 256 + threadIdx.x;
  int d = idx & 127;
  int n = (idx >> 7) & 7;
  int s = (idx >> 10) & 2047;
  int b = idx >> 21;
  size_t base = ((size_t)(b * SS + s) * (2 * NKV * HD)) + n * (2 * HD);
  float kv = g_kvproj[base + d];
  float kp = (d < 64) ? -g_kvproj[base + d + 64] : g_kvproj[base + d - 64];
  float kout = kv * cosb[s * HD + d] + kp * sinb[s * HD + d];
  size_t o = ((size_t)(b * NKV + n) * SS + s) * HD + d;
  g_k[o] = kout;
  g_v[o] = g_kvproj[base + HD + d];
}

// ---------------------------------------------------------------------------
// Causal flash attention (f32 SIMT): 32 q-rows per CTA, 32-key blocks.
// ---------------------------------------------------------------------------
__global__ __launch_bounds__(256) void attn_kernel() {
  extern __shared__ float smv[];
  float* Qs = smv;                // 32 x 128
  float* Ks = Qs + 32 * 128;      // 32 x 132 (padded)
  float* Vs = Ks + 32 * 132;      // 32 x 128
  float* Ps = Vs + 32 * 128;      // 32 x 33  (padded)

  const int b = blockIdx.z;
  const int h = blockIdx.y;
  const int q0 = blockIdx.x * 32;
  const int kvh = h / (NH / NKV);
  const int tid = threadIdx.x;
  const int r = tid >> 3;
  const int g = tid & 7;

  const float* Qg = g_q + ((size_t)(b * NH + h) * SS + q0) * HD;
  const float* Kg = g_k + (size_t)(b * NKV + kvh) * SS * HD;
  const float* Vg = g_v + (size_t)(b * NKV + kvh) * SS * HD;

#pragma unroll
  for (int i = 0; i < 4; i++) {
    int idx = tid + i * 256;
    int row = idx >> 5, c4 = idx & 31;
    *(float4*)(Qs + row * 128 + c4 * 4) = *(const float4*)(Qg + row * HD + c4 * 4);
  }

  float acc[16];
#pragma unroll
  for (int i = 0; i < 16; i++) acc[i] = 0.0f;
  float m = -1e30f, l = 0.0f;

  const float scale = 0.08838834764831845f;
  const int nkb = blockIdx.x + 1;

  for (int kb = 0; kb < nkb; kb++) {
    const int k0 = kb * 32;
#pragma unroll
    for (int i = 0; i < 4; i++) {
      int idx = tid + i * 256;
      int row = idx >> 5, c4 = idx & 31;
      *(float4*)(Ks + row * 132 + c4 * 4) = *(const float4*)(Kg + (k0 + row) * HD + c4 * 4);
      *(float4*)(Vs + row * 128 + c4 * 4) = *(const float4*)(Vg + (k0 + row) * HD + c4 * 4);
    }
    __syncthreads();

    float s0 = 0.f, s1 = 0.f, s2 = 0.f, s3 = 0.f;
    const float4* qrow = (const float4*)(Qs + r * 128);
    const float4* kr0 = (const float4*)(Ks + (g + 0) * 132);
    const float4* kr1 = (const float4*)(Ks + (g + 8) * 132);
    const float4* kr2 = (const float4*)(Ks + (g + 16) * 132);
    const float4* kr3 = (const float4*)(Ks + (g + 24) * 132);
#pragma unroll
    for (int d4 = 0; d4 < 32; d4++) {
      float4 q4 = qrow[d4];
      float4 k4;
      k4 = kr0[d4];
      s0 = fmaf(q4.x, k4.x, fmaf(q4.y, k4.y, fmaf(q4.z, k4.z, fmaf(q4.w, k4.w, s0))));
      k4 = kr1[d4];
      s1 = fmaf(q4.x, k4.x, fmaf(q4.y, k4.y, fmaf(q4.z, k4.z, fmaf(q4.w, k4.w, s1))));
      k4 = kr2[d4];
      s2 = fmaf(q4.x, k4.x, fmaf(q4.y, k4.y, fmaf(q4.z, k4.z, fmaf(q4.w, k4.w, s2))));
      k4 = kr3[d4];
      s3 = fmaf(q4.x, k4.x, fmaf(q4.y, k4.y, fmaf(q4.z, k4.z, fmaf(q4.w, k4.w, s3))));
    }
    const int qg = q0 + r;
    float sc[4] = {s0, s1, s2, s3};
#pragma unroll
    for (int jj = 0; jj < 4; jj++) {
      int kg = k0 + g + jj * 8;
      sc[jj] = sc[jj] * scale + ((kg > qg) ? -1e9f : 0.0f);
    }

    float rowmax = fmaxf(fmaxf(sc[0], sc[1]), fmaxf(sc[2], sc[3]));
#pragma unroll
    for (int msk = 1; msk < 8; msk <<= 1)
      rowmax = fmaxf(rowmax, __shfl_xor_sync(0xffffffffu, rowmax, msk));

    float m_new = fmaxf(m, rowmax);
    float corr = __expf(m - m_new);
    float p[4], psum = 0.f;
#pragma unroll
    for (int jj = 0; jj < 4; jj++) {
      p[jj] = __expf(sc[jj] - m_new);
      psum += p[jj];
    }
#pragma unroll
    for (int msk = 1; msk < 8; msk <<= 1)
      psum += __shfl_xor_sync(0xffffffffu, psum, msk);
    l = l * corr + psum;
    m = m_new;
#pragma unroll
    for (int i = 0; i < 16; i++) acc[i] *= corr;

#pragma unroll
    for (int jj = 0; jj < 4; jj++) Ps[r * 33 + g + jj * 8] = p[jj];
    __syncthreads();

#pragma unroll 4
    for (int j = 0; j < 32; j++) {
      float pv = Ps[r * 33 + j];
      const float4* vr = (const float4*)(Vs + j * 128 + g * 16);
#pragma unroll
      for (int u = 0; u < 4; u++) {
        float4 v4 = vr[u];
        acc[u * 4 + 0] = fmaf(pv, v4.x, acc[u * 4 + 0]);
        acc[u * 4 + 1] = fmaf(pv, v4.y, acc[u * 4 + 1]);
        acc[u * 4 + 2] = fmaf(pv, v4.z, acc[u * 4 + 2]);
        acc[u * 4 + 3] = fmaf(pv, v4.w, acc[u * 4 + 3]);
      }
    }
    __syncthreads();
  }

  float inv = 1.0f / l;
  float* outp = g_attn + ((size_t)(b * SS + q0 + r)) * HIDD + h * HD + g * 16;
#pragma unroll
  for (int u = 0; u < 4; u++) {
    float4 v4;
    v4.x = acc[u * 4 + 0] * inv;
    v4.y = acc[u * 4 + 1] * inv;
    v4.z = acc[u * 4 + 2] * inv;
    v4.w = acc[u * 4 + 3] * inv;
    *(float4*)(outp + u * 4) = v4;
  }
}

// ---------------------------------------------------------------------------
extern "C" void kernel_launch(void* const* d_in, const int* in_sizes, int n_in,
                              void* d_out, int out_size) {
  const float* hidden = (const float*)d_in[0];
  // d_in[1] = attention_mask (pure causal -1e9; applied analytically)
  const float* cosb = (const float*)d_in[2];
  const float* sinb = (const float*)d_in[3];
  const float* Wq = (const float*)d_in[4];
  const float* Wkv = (const float*)d_in[5];
  const float* Wd = (const float*)d_in[6];
  const float* bd = (const float*)d_in[7];
  float* out = (float*)d_out;

  float *qproj, *kvproj, *attn;
  cudaGetSymbolAddress((void**)&qproj, g_qproj);
  cudaGetSymbolAddress((void**)&kvproj, g_kvproj);
  cudaGetSymbolAddress((void**)&attn, g_attn);

  const int M = BB * SS;  // 4096
  const int gemm_smem = 2 * STAGE_FLOATS * 4;  // 73728 B

  cudaFuncSetAttribute(gemm_tf32<0>, cudaFuncAttributeMaxDynamicSharedMemorySize, gemm_smem);
  cudaFuncSetAttribute(gemm_tf32<1>, cudaFuncAttributeMaxDynamicSharedMemorySize, gemm_smem);

  // 1) Q projection: [M, 4096] = hidden @ Wq^T
  {
    dim3 grid(HIDD / BN, M / BM);
    gemm_tf32<0><<<grid, 256, gemm_smem>>>(hidden, Wq, nullptr, qproj, M, HIDD, HIDD);
  }
  // 2) KV projection: [M, 2048] = hidden @ Wkv^T
  {
    dim3 grid((2 * NKV * HD) / BN, M / BM);
    gemm_tf32<0><<<grid, 256, gemm_smem>>>(hidden, Wkv, nullptr, kvproj, M, 2 * NKV * HD, HIDD);
  }
  // 3) RoPE + scatter
  rope_q_kernel<<<(BB * SS * HIDD) / 256, 256>>>(cosb, sinb);
  rope_kv_kernel<<<(BB * SS * NKV * HD) / 256, 256>>>(cosb, sinb);

  // 4) attention
  {
    int smem = (32 * 128 + 32 * 132 + 32 * 128 + 32 * 33) * 4;  // 53888 B
    cudaFuncSetAttribute(attn_kernel, cudaFuncAttributeMaxDynamicSharedMemorySize, smem);
    dim3 grid(SS / 32, NH, BB);
    attn_kernel<<<grid, 256, smem>>>();
  }

  // 5) output projection with bias: out = attn @ Wd^T + bd
  {
    dim3 grid(HIDD / BN, M / BM);
    gemm_tf32<1><<<grid, 256, gemm_smem>>>(attn, Wd, bd, out, M, HIDD, HIDD);
  }
}

// round 7
// speedup vs baseline: 4.9180x; 3.5740x over previous
#include <cuda_runtime.h>
#include <cstdint>

// Problem constants
#define BB   2
#define SS   2048
#define HIDD 4096
#define NH   32
#define NKV  8
#define HD   128

// GEMM tiling
#define BM 128
#define BN 128
#define BKK 32
#define LDK 36
#define STAGE_FLOATS ((BM + BN) * LDK)

// Attention tiling / smem layout (floats)
#define ATT_LDQ 132
#define ATT_LDK 132
#define ATT_LDV 136
#define ATT_LDP 36
#define QS_OFF 0
#define KH_OFF (128 * ATT_LDQ)              // 16896
#define KCHUNK (32 * ATT_LDK)               // 4224  (Khi0,Khi1,Klo0,Klo1)
#define VH_OFF (KH_OFF + 4 * KCHUNK)        // 33792 (Vhi0,Vhi1,Vlo0,Vlo1)
#define VCHUNK (32 * ATT_LDV)               // 4352
#define PS_OFF (VH_OFF + 4 * VCHUNK)        // 51200
#define ATT_SMEM ((PS_OFF + 8 * 16 * ATT_LDP) * 4)  // 223232 bytes

// ---------------- scratch (static device globals; no runtime alloc) --------
__device__ float g_qproj[(size_t)BB * SS * HIDD];
__device__ float g_kvproj[(size_t)BB * SS * 2 * NKV * HD];
__device__ float g_q[(size_t)BB * NH * SS * HD];
__device__ float g_khi[(size_t)BB * NKV * SS * HD];
__device__ float g_klo[(size_t)BB * NKV * SS * HD];
__device__ float g_vhi[(size_t)BB * NKV * SS * HD];
__device__ float g_vlo[(size_t)BB * NKV * SS * HD];
__device__ float g_attn[(size_t)BB * SS * HIDD];

// ---------------------------------------------------------------------------
// helpers
// ---------------------------------------------------------------------------
__device__ __forceinline__ uint32_t cvta_smem(const void* p) {
  return (uint32_t)__cvta_generic_to_shared(p);
}

__device__ __forceinline__ void cp_async16(uint32_t saddr, const void* gptr) {
  asm volatile("cp.async.cg.shared.global [%0], [%1], 16;\n" ::"r"(saddr), "l"(gptr));
}

__device__ __forceinline__ uint32_t f2tf32(float x) {
  uint32_t u;
  asm("cvt.rna.tf32.f32 %0, %1;\n" : "=r"(u) : "f"(x));
  return u;
}

__device__ __forceinline__ void mma_tf32(float* c, const uint32_t* a, const uint32_t* b) {
  asm volatile(
      "mma.sync.aligned.m16n8k8.row.col.f32.tf32.tf32.f32 "
      "{%0,%1,%2,%3}, {%4,%5,%6,%7}, {%8,%9}, {%0,%1,%2,%3};\n"
      : "+f"(c[0]), "+f"(c[1]), "+f"(c[2]), "+f"(c[3])
      : "r"(a[0]), "r"(a[1]), "r"(a[2]), "r"(a[3]), "r"(b[0]), "r"(b[1]));
}

// ---------------------------------------------------------------------------
// TF32 tensor-core GEMM: C[M,N] = A[M,K] @ W[N,K]^T (+ bias[N])  (unchanged)
// ---------------------------------------------------------------------------
template <int BIAS>
__global__ __launch_bounds__(256, 2) void gemm_tf32(const float* __restrict__ A,
                                                    const float* __restrict__ W,
                                                    const float* __restrict__ bias,
                                                    float* __restrict__ C,
                                                    int M, int N, int K) {
  extern __shared__ float sm[];
  const int bm = blockIdx.y * BM;
  const int bn = blockIdx.x * BN;
  const int tid = threadIdx.x;
  const int warp = tid >> 5;
  const int lane = tid & 31;
  const int g = lane >> 2;
  const int t = lane & 3;
  const int wm = (warp >> 2) * 64;
  const int wn = (warp & 3) * 32;

  const float* Ag = A + (size_t)bm * K;
  const float* Wg = W + (size_t)bn * K;
  const int KT = K / BKK;

  float acc[4][4][4];
#pragma unroll
  for (int mi = 0; mi < 4; mi++)
#pragma unroll
    for (int ni = 0; ni < 4; ni++)
#pragma unroll
      for (int c = 0; c < 4; c++) acc[mi][ni][c] = 0.0f;

  auto issue = [&](int kb) {
    float* As = sm + (kb & 1) * STAGE_FLOATS;
    float* Ws = As + BM * LDK;
    int k0 = kb * BKK;
#pragma unroll
    for (int i = 0; i < 4; i++) {
      int lin = tid + i * 256;
      int row = lin >> 3;
      int c4 = lin & 7;
      cp_async16(cvta_smem(As + row * LDK + c4 * 4), Ag + (size_t)row * K + k0 + c4 * 4);
      cp_async16(cvta_smem(Ws + row * LDK + c4 * 4), Wg + (size_t)row * K + k0 + c4 * 4);
    }
    asm volatile("cp.async.commit_group;\n" ::);
  };

  issue(0);

  for (int kb = 0; kb < KT; kb++) {
    if (kb + 1 < KT) {
      issue(kb + 1);
      asm volatile("cp.async.wait_group 1;\n" ::);
    } else {
      asm volatile("cp.async.wait_group 0;\n" ::);
    }
    __syncthreads();

    const float* As = sm + (kb & 1) * STAGE_FLOATS;
    const float* Ws = As + BM * LDK;

#pragma unroll
    for (int ks = 0; ks < 4; ks++) {
      const int k0 = ks * 8;
      uint32_t af[4][4];
      uint32_t bf[4][2];
#pragma unroll
      for (int mi = 0; mi < 4; mi++) {
        const float* p0 = As + (wm + mi * 16 + g) * LDK + k0 + t;
        const float* p1 = p0 + 8 * LDK;
        af[mi][0] = f2tf32(p0[0]);
        af[mi][1] = f2tf32(p1[0]);
        af[mi][2] = f2tf32(p0[4]);
        af[mi][3] = f2tf32(p1[4]);
      }
#pragma unroll
      for (int ni = 0; ni < 4; ni++) {
        const float* p = Ws + (wn + ni * 8 + g) * LDK + k0 + t;
        bf[ni][0] = f2tf32(p[0]);
        bf[ni][1] = f2tf32(p[4]);
      }
#pragma unroll
      for (int mi = 0; mi < 4; mi++)
#pragma unroll
        for (int ni = 0; ni < 4; ni++) mma_tf32(acc[mi][ni], af[mi], bf[ni]);
    }
    __syncthreads();
  }

#pragma unroll
  for (int mi = 0; mi < 4; mi++) {
    int row0 = bm + wm + mi * 16 + g;
#pragma unroll
    for (int ni = 0; ni < 4; ni++) {
      int col = bn + wn + ni * 8 + t * 2;
      float b0 = 0.f, b1 = 0.f;
      if (BIAS) { b0 = bias[col]; b1 = bias[col + 1]; }
      float2 v0 = make_float2(acc[mi][ni][0] + b0, acc[mi][ni][1] + b1);
      float2 v1 = make_float2(acc[mi][ni][2] + b0, acc[mi][ni][3] + b1);
      *(float2*)(C + (size_t)row0 * N + col) = v0;
      *(float2*)(C + (size_t)(row0 + 8) * N + col) = v1;
    }
  }
}

// ---------------------------------------------------------------------------
// RoPE for Q + scatter to [B, NH, S, HD]
// ---------------------------------------------------------------------------
__global__ __launch_bounds__(256) void rope_q_kernel(
    const float* __restrict__ cosb, const float* __restrict__ sinb) {
  int idx = blockIdx.x * 256 + threadIdx.x;
  int d = idx & 127;
  int h = (idx >> 7) & 31;
  int s = (idx >> 12) & 2047;
  int b = idx >> 23;
  float v = g_qproj[idx];
  float p = (d < 64) ? -g_qproj[idx + 64] : g_qproj[idx - 64];
  float out = v * cosb[s * HD + d] + p * sinb[s * HD + d];
  g_q[((size_t)(b * NH + h) * SS + s) * HD + d] = out;
}

// ---------------------------------------------------------------------------
// RoPE for K + scatter K/V as tf32 hi/lo pairs to [B, NKV, S, HD]
// ---------------------------------------------------------------------------
__global__ __launch_bounds__(256) void rope_kv_kernel(
    const float* __restrict__ cosb, const float* __restrict__ sinb) {
  int idx = blockIdx.x * 256 + threadIdx.x;
  int d = idx & 127;
  int n = (idx >> 7) & 7;
  int s = (idx >> 10) & 2047;
  int b = idx >> 21;
  size_t base = ((size_t)(b * SS + s) * (2 * NKV * HD)) + n * (2 * HD);
  float kv = g_kvproj[base + d];
  float kp = (d < 64) ? -g_kvproj[base + d + 64] : g_kvproj[base + d - 64];
  float kout = kv * cosb[s * HD + d] + kp * sinb[s * HD + d];
  float vout = g_kvproj[base + HD + d];
  size_t o = ((size_t)(b * NKV + n) * SS + s) * HD + d;
  float kh = __uint_as_float(f2tf32(kout));
  float vh = __uint_as_float(f2tf32(vout));
  g_khi[o] = kh;
  g_klo[o] = kout - kh;
  g_vhi[o] = vh;
  g_vlo[o] = vout - vh;
}

// ---------------------------------------------------------------------------
// Tensor-core causal flash attention, 3xTF32 compensated.
// 128 q-rows per CTA, 32-key blocks, 8 warps (16 q-rows each), 256 threads.
// K/V hi/lo double-buffered via cp.async (1-block prefetch).
// ---------------------------------------------------------------------------
__global__ __launch_bounds__(256, 1) void attn_mma_kernel() {
  extern __shared__ float sm[];
  const int b = blockIdx.z;
  const int h = blockIdx.y;
  const int qb = (int)gridDim.x - 1 - (int)blockIdx.x;  // big tiles first
  const int q0 = qb * 128;
  const int kvh = h >> 2;  // NH/NKV = 4
  const int tid = threadIdx.x;
  const int warp = tid >> 5;
  const int lane = tid & 31;
  const int g = lane >> 2;
  const int t = lane & 3;
  const int wm = warp * 16;

  float* Qs = sm;
  float* Pw = sm + PS_OFF + warp * (16 * ATT_LDP);

  const float* Qg = g_q + ((size_t)(b * NH + h) * SS + q0) * HD;
  const size_t kvbase = (size_t)(b * NKV + kvh) * SS * HD;
  const float* Khg = g_khi + kvbase;
  const float* Klg = g_klo + kvbase;
  const float* Vhg = g_vhi + kvbase;
  const float* Vlg = g_vlo + kvbase;

  const int nkb = 4 * qb + 4;

  auto cta_copy_tile = [&](float* dst, const float* src, int ld) {
#pragma unroll
    for (int i = 0; i < 4; i++) {
      int lin = tid + i * 256;
      int row = lin >> 5, c4 = lin & 31;
      cp_async16(cvta_smem(dst + row * ld + c4 * 4), src + row * HD + c4 * 4);
    }
  };
  auto loadKV = [&](int kb) {
    int buf = kb & 1;
    size_t off = (size_t)kb * 32 * HD;
    cta_copy_tile(sm + KH_OFF + buf * KCHUNK, Khg + off, ATT_LDK);
    cta_copy_tile(sm + KH_OFF + 2 * KCHUNK + buf * KCHUNK, Klg + off, ATT_LDK);
    cta_copy_tile(sm + VH_OFF + buf * VCHUNK, Vhg + off, ATT_LDV);
    cta_copy_tile(sm + VH_OFF + 2 * VCHUNK + buf * VCHUNK, Vlg + off, ATT_LDV);
  };

  // prologue: Q tile + K/V(0) in group G(-1)
#pragma unroll
  for (int i = 0; i < 16; i++) {
    int lin = tid + i * 256;
    int row = lin >> 5, c4 = lin & 31;
    cp_async16(cvta_smem(Qs + row * ATT_LDQ + c4 * 4), Qg + row * HD + c4 * 4);
  }
  loadKV(0);
  asm volatile("cp.async.commit_group;\n" ::);

  float oacc[16][4];
#pragma unroll
  for (int i = 0; i < 16; i++)
#pragma unroll
    for (int c = 0; c < 4; c++) oacc[i][c] = 0.0f;
  float mrow0 = -1e30f, mrow1 = -1e30f, lrow0 = 0.0f, lrow1 = 0.0f;
  const float scale = 0.08838834764831845f;  // 1/sqrt(128)

  for (int kb = 0; kb < nkb; kb++) {
    __syncthreads();  // all warps done with buf (kb+1)&1 before refill
    if (kb + 1 < nkb) loadKV(kb + 1);
    asm volatile("cp.async.commit_group;\n" ::);
    asm volatile("cp.async.wait_group 1;\n" ::);  // waits loads for kb
    __syncthreads();

    const float* Kh = sm + KH_OFF + (kb & 1) * KCHUNK;
    const float* Kl = Kh + 2 * KCHUNK;
    const float* Vh = sm + VH_OFF + (kb & 1) * VCHUNK;
    const float* Vl = Vh + 2 * VCHUNK;

    // ---- S = Q K^T (3xTF32), even/odd-kstep partial accumulators ----
    float sacc[2][4][4];
#pragma unroll
    for (int u = 0; u < 2; u++)
#pragma unroll
      for (int nf = 0; nf < 4; nf++)
#pragma unroll
        for (int c = 0; c < 4; c++) sacc[u][nf][c] = 0.0f;

#pragma unroll
    for (int kp = 0; kp < 8; kp++) {
      uint32_t ah[2][4], al[2][4], bh[2][4][2], bl[2][4][2];
#pragma unroll
      for (int u = 0; u < 2; u++) {
        const int k0 = (kp * 2 + u) * 8;
        const float* qp = Qs + (wm + g) * ATT_LDQ + k0 + t;
        float q0f = qp[0];
        float q1f = qp[8 * ATT_LDQ];
        float q2f = qp[4];
        float q3f = qp[8 * ATT_LDQ + 4];
        ah[u][0] = f2tf32(q0f); al[u][0] = __float_as_uint(q0f - __uint_as_float(ah[u][0]));
        ah[u][1] = f2tf32(q1f); al[u][1] = __float_as_uint(q1f - __uint_as_float(ah[u][1]));
        ah[u][2] = f2tf32(q2f); al[u][2] = __float_as_uint(q2f - __uint_as_float(ah[u][2]));
        ah[u][3] = f2tf32(q3f); al[u][3] = __float_as_uint(q3f - __uint_as_float(ah[u][3]));
#pragma unroll
        for (int nf = 0; nf < 4; nf++) {
          const float* kh0 = Kh + (nf * 8 + g) * ATT_LDK + k0 + t;
          const float* kl0 = Kl + (nf * 8 + g) * ATT_LDK + k0 + t;
          bh[u][nf][0] = __float_as_uint(kh0[0]);
          bh[u][nf][1] = __float_as_uint(kh0[4]);
          bl[u][nf][0] = __float_as_uint(kl0[0]);
          bl[u][nf][1] = __float_as_uint(kl0[4]);
        }
      }
#pragma unroll
      for (int u = 0; u < 2; u++)
#pragma unroll
        for (int nf = 0; nf < 4; nf++) mma_tf32(sacc[u][nf], ah[u], bh[u][nf]);
#pragma unroll
      for (int u = 0; u < 2; u++)
#pragma unroll
        for (int nf = 0; nf < 4; nf++) mma_tf32(sacc[u][nf], al[u], bh[u][nf]);
#pragma unroll
      for (int u = 0; u < 2; u++)
#pragma unroll
        for (int nf = 0; nf < 4; nf++) mma_tf32(sacc[u][nf], ah[u], bl[u][nf]);
    }

    // ---- softmax (online) ----
    float s[4][4];
#pragma unroll
    for (int nf = 0; nf < 4; nf++)
#pragma unroll
      for (int c = 0; c < 4; c++) s[nf][c] = (sacc[0][nf][c] + sacc[1][nf][c]) * scale;

    if (kb * 32 + 31 > q0 + wm) {  // warp-uniform; rows wm..wm+15
      const int r0i = q0 + wm + g;
      const int r1i = r0i + 8;
#pragma unroll
      for (int nf = 0; nf < 4; nf++) {
        int colb = kb * 32 + nf * 8 + 2 * t;
        if (colb > r0i) s[nf][0] = -1e9f;
        if (colb + 1 > r0i) s[nf][1] = -1e9f;
        if (colb > r1i) s[nf][2] = -1e9f;
        if (colb + 1 > r1i) s[nf][3] = -1e9f;
      }
    }

    float m0 = -1e30f, m1 = -1e30f;
#pragma unroll
    for (int nf = 0; nf < 4; nf++) {
      m0 = fmaxf(m0, fmaxf(s[nf][0], s[nf][1]));
      m1 = fmaxf(m1, fmaxf(s[nf][2], s[nf][3]));
    }
    m0 = fmaxf(m0, __shfl_xor_sync(0xffffffffu, m0, 1));
    m0 = fmaxf(m0, __shfl_xor_sync(0xffffffffu, m0, 2));
    m1 = fmaxf(m1, __shfl_xor_sync(0xffffffffu, m1, 1));
    m1 = fmaxf(m1, __shfl_xor_sync(0xffffffffu, m1, 2));

    float nm0 = fmaxf(mrow0, m0), nm1 = fmaxf(mrow1, m1);
    float c0 = __expf(mrow0 - nm0), c1 = __expf(mrow1 - nm1);
    float r0 = 0.0f, r1 = 0.0f;
#pragma unroll
    for (int nf = 0; nf < 4; nf++) {
      float p00 = __expf(s[nf][0] - nm0);
      float p01 = __expf(s[nf][1] - nm0);
      float p10 = __expf(s[nf][2] - nm1);
      float p11 = __expf(s[nf][3] - nm1);
      r0 += p00 + p01;
      r1 += p10 + p11;
      *(float2*)(Pw + g * ATT_LDP + nf * 8 + 2 * t) = make_float2(p00, p01);
      *(float2*)(Pw + (g + 8) * ATT_LDP + nf * 8 + 2 * t) = make_float2(p10, p11);
    }
    r0 += __shfl_xor_sync(0xffffffffu, r0, 1);
    r0 += __shfl_xor_sync(0xffffffffu, r0, 2);
    r1 += __shfl_xor_sync(0xffffffffu, r1, 1);
    r1 += __shfl_xor_sync(0xffffffffu, r1, 2);
    lrow0 = lrow0 * c0 + r0;
    lrow1 = lrow1 * c1 + r1;
    mrow0 = nm0;
    mrow1 = nm1;
#pragma unroll
    for (int i = 0; i < 16; i++) {
      oacc[i][0] *= c0;
      oacc[i][1] *= c0;
      oacc[i][2] *= c1;
      oacc[i][3] *= c1;
    }
    __syncwarp();  // P stores visible to all lanes of this warp

    // ---- O += P V (3xTF32) ----
#pragma unroll
    for (int ks = 0; ks < 4; ks++) {
      const int k0 = ks * 8;
      const float* pp = Pw + g * ATT_LDP + k0 + t;
      float p0f = pp[0];
      float p1f = pp[8 * ATT_LDP];
      float p2f = pp[4];
      float p3f = pp[8 * ATT_LDP + 4];
      uint32_t pah[4], pal[4];
      pah[0] = f2tf32(p0f); pal[0] = __float_as_uint(p0f - __uint_as_float(pah[0]));
      pah[1] = f2tf32(p1f); pal[1] = __float_as_uint(p1f - __uint_as_float(pah[1]));
      pah[2] = f2tf32(p2f); pal[2] = __float_as_uint(p2f - __uint_as_float(pah[2]));
      pah[3] = f2tf32(p3f); pal[3] = __float_as_uint(p3f - __uint_as_float(pah[3]));
#pragma unroll
      for (int nh = 0; nh < 2; nh++) {
        uint32_t vbh[8][2], vbl[8][2];
#pragma unroll
        for (int j = 0; j < 8; j++) {
          int n0 = (nh * 8 + j) * 8 + g;
          const float* vp = Vh + (k0 + t) * ATT_LDV + n0;
          const float* vl = Vl + (k0 + t) * ATT_LDV + n0;
          vbh[j][0] = __float_as_uint(vp[0]);
          vbh[j][1] = __float_as_uint(vp[4 * ATT_LDV]);
          vbl[j][0] = __float_as_uint(vl[0]);
          vbl[j][1] = __float_as_uint(vl[4 * ATT_LDV]);
        }
#pragma unroll
        for (int j = 0; j < 8; j++) mma_tf32(oacc[nh * 8 + j], pah, vbh[j]);
#pragma unroll
        for (int j = 0; j < 8; j++) mma_tf32(oacc[nh * 8 + j], pal, vbh[j]);
#pragma unroll
        for (int j = 0; j < 8; j++) mma_tf32(oacc[nh * 8 + j], pah, vbl[j]);
      }
    }
  }

  // ---- epilogue ----
  float inv0 = 1.0f / lrow0;
  float inv1 = 1.0f / lrow1;
  const int row0 = q0 + wm + g;
  float* o0 = g_attn + ((size_t)(b * SS) + row0) * HIDD + h * HD;
  float* o1 = o0 + (size_t)8 * HIDD;
#pragma unroll
  for (int nf = 0; nf < 16; nf++) {
    *(float2*)(o0 + nf * 8 + 2 * t) = make_float2(oacc[nf][0] * inv0, oacc[nf][1] * inv0);
    *(float2*)(o1 + nf * 8 + 2 * t) = make_float2(oacc[nf][2] * inv1, oacc[nf][3] * inv1);
  }
}

// ---------------------------------------------------------------------------
extern "C" void kernel_launch(void* const* d_in, const int* in_sizes, int n_in,
                              void* d_out, int out_size) {
  const float* hidden = (const float*)d_in[0];
  // d_in[1] = attention_mask (pure causal; applied analytically)
  const float* cosb = (const float*)d_in[2];
  const float* sinb = (const float*)d_in[3];
  const float* Wq = (const float*)d_in[4];
  const float* Wkv = (const float*)d_in[5];
  const float* Wd = (const float*)d_in[6];
  const float* bd = (const float*)d_in[7];
  float* out = (float*)d_out;

  float *qproj, *kvproj, *attn;
  cudaGetSymbolAddress((void**)&qproj, g_qproj);
  cudaGetSymbolAddress((void**)&kvproj, g_kvproj);
  cudaGetSymbolAddress((void**)&attn, g_attn);

  const int M = BB * SS;
  const int gemm_smem = 2 * STAGE_FLOATS * 4;

  cudaFuncSetAttribute(gemm_tf32<0>, cudaFuncAttributeMaxDynamicSharedMemorySize, gemm_smem);
  cudaFuncSetAttribute(gemm_tf32<1>, cudaFuncAttributeMaxDynamicSharedMemorySize, gemm_smem);
  cudaFuncSetAttribute(attn_mma_kernel, cudaFuncAttributeMaxDynamicSharedMemorySize, ATT_SMEM);

  // 1) Q projection
  {
    dim3 grid(HIDD / BN, M / BM);
    gemm_tf32<0><<<grid, 256, gemm_smem>>>(hidden, Wq, nullptr, qproj, M, HIDD, HIDD);
  }
  // 2) KV projection
  {
    dim3 grid((2 * NKV * HD) / BN, M / BM);
    gemm_tf32<0><<<grid, 256, gemm_smem>>>(hidden, Wkv, nullptr, kvproj, M, 2 * NKV * HD, HIDD);
  }
  // 3) RoPE + scatter (K/V split into tf32 hi/lo)
  rope_q_kernel<<<(BB * SS * HIDD) / 256, 256>>>(cosb, sinb);
  rope_kv_kernel<<<(BB * SS * NKV * HD) / 256, 256>>>(cosb, sinb);

  // 4) tensor-core flash attention
  {
    dim3 grid(SS / 128, NH, BB);
    attn_mma_kernel<<<grid, 256, ATT_SMEM>>>();
  }

  // 5) output projection with bias
  {
    dim3 grid(HIDD / BN, M / BM);
    gemm_tf32<1><<<grid, 256, gemm_smem>>>(attn, Wd, bd, out, M, HIDD, HIDD);
  }
}